// round 14
// baseline (speedup 1.0000x reference)
#include <cuda_runtime.h>
#include <math.h>

// Shapes (fixed by the problem)
#define BB 64      // batch
#define TT 512     // seq len
#define EE 256     // embed dim
#define HH 512     // hidden
#define G3 1536    // 3*H
#define HR 516     // padded smem row stride for h (floats)
#define SMS 132    // GEMM A smem row stride (floats)
#define SBS 140    // GEMM B smem row stride (floats, swizzled chunks)

typedef unsigned long long ull;

// ---------------- scratch (device globals; no allocation allowed) ------------
__device__ float g_x0[(size_t)BB * TT * EE];             // [B*T][256]   embeddings
__device__ float g_xg[(size_t)2 * TT * BB * G3];         // [dir][t][b][3H] input-gate proj
__device__ float g_out0[(size_t)BB * TT * 2 * HH];       // [b][t][2H]   layer-0 outputs
__device__ float g_h[(size_t)2 * 2 * BB * HH];           // [dir][buf][b][H] ping-pong state
__device__ unsigned g_cnt[128];                          // per-group barrier counters (sep lines)
__device__ volatile unsigned g_gen[128];

// ---------------- f32x2 packed helpers ----------------
__device__ __forceinline__ ull f2pack(float x, float y) {
    ull r; asm("mov.b64 %0,{%1,%2};" : "=l"(r) : "f"(x), "f"(y)); return r;
}
__device__ __forceinline__ ull ffma2(ull a, ull b, ull c) {
    ull d; asm("fma.rn.f32x2 %0,%1,%2,%3;" : "=l"(d) : "l"(a), "l"(b), "l"(c)); return d;
}
__device__ __forceinline__ void f2unpack(ull p, float& x, float& y) {
    asm("mov.b64 {%0,%1},%2;" : "=f"(x), "=f"(y) : "l"(p));
}

// B-tile column swizzle: spread 32-float-periodic chunks across bank groups
__device__ __forceinline__ int bswz(int c) { return c + ((c >> 5) << 2); }

// ---------------- split atomic-counter grid barrier (32-CTA groups) ----------
// arrive: publish + count in; returns (on thread 0) the generation to wait past.
__device__ __forceinline__ unsigned grp_arrive(int gid) {
    __threadfence();
    __syncthreads();
    unsigned my = 0;
    if (threadIdx.x == 0) {
        volatile unsigned* gen = &g_gen[gid * 32];
        my = *gen;
        if (atomicAdd(&g_cnt[gid * 32], 1) == 31) {
            atomicExch(&g_cnt[gid * 32], 0);
            __threadfence();
            *gen = my + 1;
        }
    }
    return my;   // meaningful on thread 0 only
}
__device__ __forceinline__ void grp_wait(int gid, unsigned my) {
    if (threadIdx.x == 0) {
        volatile unsigned* gen = &g_gen[gid * 32];
        while (*gen == my) { }
    }
    __syncthreads();
    __threadfence();
}

// ---------------- embedding gather ----------------
__global__ void embed_kernel(const int* __restrict__ sent, const float* __restrict__ emb) {
    int row = blockIdx.x;                 // row = b*T + t
    int idx = sent[row];
    const float4* src = (const float4*)(emb + (size_t)idx * EE);
    float4* dst = (float4*)(g_x0 + (size_t)row * EE);
    dst[threadIdx.x] = src[threadIdx.x];  // 64 threads * float4 = 256 floats
}

// ---------------- input projection GEMM (f32x2, A-pairs x dup-B) -------------
// xg[dir][t][b][g] = A[b*T+t][:] . W[dir][g][:] + b_ih
// Tile 128x128, BK=16, 8x8 microtile. A pairs from consecutive smem (LDS.128);
// B scalars duplicated in registers. B smem chunk-swizzled -> conflict-free LDS.
__global__ __launch_bounds__(256, 2) void inproj_kernel(const float* __restrict__ W,
                                                        const float* __restrict__ bias,
                                                        int K, int layer) {
    const float* A = (layer == 0) ? g_x0 : g_out0;
    __shared__ __align__(16) float sA[2][16][SMS];
    __shared__ __align__(16) float sB[2][16][SBS];

    const int m0 = blockIdx.x * 128, n0 = blockIdx.y * 128, dir = blockIdx.z;
    const float* Wd = W + (size_t)dir * G3 * K;
    const int tid = threadIdx.x;
    const int lr = tid >> 2, lc = tid & 3;     // loader: 64 rows x 4 float4-cols (coalesced)
    const int ty = tid >> 4, tx = tid & 15;    // compute: 16x16 threads, 8x8 outputs
    const float* Ar0 = A + (size_t)(m0 + lr) * K + lc * 4;
    const float* Ar1 = A + (size_t)(m0 + lr + 64) * K + lc * 4;
    const float* Br0 = Wd + (size_t)(n0 + lr) * K + lc * 4;
    const float* Br1 = Wd + (size_t)(n0 + lr + 64) * K + lc * 4;
    const int bw0 = bswz(lr), bw1 = bswz(lr + 64);
    const int bidx = 2 * tx + (tx >> 2);       // swizzled float4 index for B reads

    ull acc[4][8];
    #pragma unroll
    for (int i = 0; i < 4; i++)
        #pragma unroll
        for (int j = 0; j < 8; j++) acc[i][j] = 0ull;

    // preload tile 0 into buf 0
    {
        float4 a0 = *(const float4*)Ar0;
        float4 a1 = *(const float4*)Ar1;
        float4 b0 = *(const float4*)Br0;
        float4 b1 = *(const float4*)Br1;
        float av0[4] = {a0.x, a0.y, a0.z, a0.w}, av1[4] = {a1.x, a1.y, a1.z, a1.w};
        float bv0[4] = {b0.x, b0.y, b0.z, b0.w}, bv1[4] = {b1.x, b1.y, b1.z, b1.w};
        #pragma unroll
        for (int e = 0; e < 4; e++) {
            sA[0][lc * 4 + e][lr] = av0[e];  sA[0][lc * 4 + e][lr + 64] = av1[e];
            sB[0][lc * 4 + e][bw0] = bv0[e]; sB[0][lc * 4 + e][bw1] = bv1[e];
        }
    }
    __syncthreads();

    const int KT = K / 16;
    for (int kt = 0; kt < KT; kt++) {
        const int buf = kt & 1;
        float4 a0, a1, b0, b1;
        const bool more = (kt + 1 < KT);
        if (more) {
            a0 = *(const float4*)(Ar0 + (kt + 1) * 16);
            a1 = *(const float4*)(Ar1 + (kt + 1) * 16);
            b0 = *(const float4*)(Br0 + (kt + 1) * 16);
            b1 = *(const float4*)(Br1 + (kt + 1) * 16);
        }
        #pragma unroll
        for (int k = 0; k < 16; k++) {
            const ulonglong2* Ak = (const ulonglong2*)&sA[buf][k][ty * 8];
            ulonglong2 aa = Ak[0], ab = Ak[1];                 // 4 M-pairs
            ull ap[4] = {aa.x, aa.y, ab.x, ab.y};
            const float4* Bk = (const float4*)&sB[buf][k][0];
            float4 b03 = Bk[bidx], b47 = Bk[bidx + 1];
            ull bd[8];
            bd[0] = f2pack(b03.x, b03.x); bd[1] = f2pack(b03.y, b03.y);
            bd[2] = f2pack(b03.z, b03.z); bd[3] = f2pack(b03.w, b03.w);
            bd[4] = f2pack(b47.x, b47.x); bd[5] = f2pack(b47.y, b47.y);
            bd[6] = f2pack(b47.z, b47.z); bd[7] = f2pack(b47.w, b47.w);
            #pragma unroll
            for (int i = 0; i < 4; i++)
                #pragma unroll
                for (int j = 0; j < 8; j++)
                    acc[i][j] = ffma2(ap[i], bd[j], acc[i][j]);
        }
        if (more) {
            const int nb = buf ^ 1;
            float av0[4] = {a0.x, a0.y, a0.z, a0.w}, av1[4] = {a1.x, a1.y, a1.z, a1.w};
            float bv0[4] = {b0.x, b0.y, b0.z, b0.w}, bv1[4] = {b1.x, b1.y, b1.z, b1.w};
            #pragma unroll
            for (int e = 0; e < 4; e++) {
                sA[nb][lc * 4 + e][lr] = av0[e];  sA[nb][lc * 4 + e][lr + 64] = av1[e];
                sB[nb][lc * 4 + e][bw0] = bv0[e]; sB[nb][lc * 4 + e][bw1] = bv1[e];
            }
        }
        __syncthreads();
    }

    // epilogue: +bias, scatter into g_xg[dir][t][b][3H]
    const int nv = n0 + tx * 8;
    const float* bp = bias + dir * G3 + nv;
    float4 bb0 = *(const float4*)bp;
    float4 bb1 = *(const float4*)(bp + 4);
    float bsv[8] = {bb0.x, bb0.y, bb0.z, bb0.w, bb1.x, bb1.y, bb1.z, bb1.w};
    #pragma unroll
    for (int i = 0; i < 4; i++) {
        float lo[8], hi[8];
        #pragma unroll
        for (int j = 0; j < 8; j++) f2unpack(acc[i][j], lo[j], hi[j]);
        int m = m0 + ty * 8 + 2 * i;
        #pragma unroll
        for (int h = 0; h < 2; h++) {
            int mm = m + h;
            int b_ = mm >> 9, t_ = mm & 511;        // m = b*512 + t
            float* dst = g_xg + (((size_t)dir * TT + t_) * BB + b_) * G3 + nv;
            const float* v = h ? hi : lo;
            float4 o0, o1;
            o0.x = v[0] + bsv[0]; o0.y = v[1] + bsv[1]; o0.z = v[2] + bsv[2]; o0.w = v[3] + bsv[3];
            o1.x = v[4] + bsv[4]; o1.y = v[5] + bsv[5]; o1.z = v[6] + bsv[6]; o1.w = v[7] + bsv[7];
            *(float4*)dst = o0;
            *(float4*)(dst + 4) = o1;
        }
    }
}

// ---------------- persistent GRU scan (one launch per layer) ----------------
// grid = 128 CTAs x 512 threads: dir(2) x bhalf(2: 32 batches) x ublk(32: 16 units).
// 1 CTA/SM, 16 warps -> 4 warps/SMSP so shfl/LDS/L2 latency hides behind FMA.
// warp w -> 1 unit (3 w_hh rows as f32x2 pairs, register-resident all 512 steps).
// Batch quads {g, g+8, g+16, g+24} reduced through one shared butterfly tree.
// Sync = atomic counter+generation barrier per (dir,bhalf) group of 32 CTAs.
__global__ __launch_bounds__(512, 1) void scan_kernel(const float* __restrict__ w_hh,
                                                      const float* __restrict__ b_hh,
                                                      int layer) {
    extern __shared__ float hs[];  // [32][HR] staged h_old (this CTA's 32 batches)
    const int bid = blockIdx.x;
    const int dir = bid >> 6;
    const int rr = bid & 63;
    const int bhalf = rr >> 5;
    const int ublk = rr & 31;
    const int gid = dir * 2 + bhalf;       // barrier group (32 CTAs)
    const int tid = threadIdx.x;
    const int wid = tid >> 5, lane = tid & 31;
    const int u = ublk * 16 + wid;         // this warp's hidden unit

    // Preload recurrent weights as f32x2 pairs: row g, pair c*2+q <-> k=c*128+lane*4+2q
    ull wf2[3][8];
    float bhh[3];
    #pragma unroll
    for (int g = 0; g < 3; g++) {
        int row = g * HH + u;
        const float4* wr = (const float4*)(w_hh + ((size_t)dir * G3 + row) * HH);
        #pragma unroll
        for (int c = 0; c < 4; c++) {
            float4 wv = __ldg(wr + c * 32 + lane);
            wf2[g][c * 2 + 0] = f2pack(wv.x, wv.y);
            wf2[g][c * 2 + 1] = f2pack(wv.z, wv.w);
        }
        bhh[g] = __ldg(b_hh + dir * G3 + row);
    }

    // zero h[dir][buf0] slice: 32 batches x 16 units = 512 elems, 1 per thread
    {
        float* z = g_h + (size_t)(dir * 2 + 0) * BB * HH;
        int bl = tid >> 4, uu = tid & 15;
        z[(size_t)(bhalf * 32 + bl) * HH + ublk * 16 + uu] = 0.f;
    }
    {
        unsigned my = grp_arrive(gid);
        grp_wait(gid, my);
    }

    const int bglob = bhalf * 32 + lane;

    // prefetch step-0 xg
    int t0 = dir ? (TT - 1) : 0;
    const float* xgb0 = g_xg + (((size_t)dir * TT + t0) * BB + bglob) * G3;
    float xr = __ldg(xgb0 + u);
    float xz = __ldg(xgb0 + HH + u);
    float xn = __ldg(xgb0 + 2 * HH + u);

    for (int s = 0; s < TT; s++) {
        const int t = dir ? (TT - 1 - s) : s;
        const int bufo = s & 1;
        const int bufn = bufo ^ 1;

        // stage h_old[32 batches][512] into padded smem (L2 reads, bypass L1)
        // 4096 float4 over 512 threads = 8 per thread
        {
            const float4* hsrc = (const float4*)(g_h + ((size_t)(dir * 2 + bufo) * BB + bhalf * 32) * HH);
            float4* hs4 = (float4*)hs;
            #pragma unroll
            for (int p = 0; p < 8; p++) {
                int idx = tid + p * 512;
                int b = idx >> 7, c = idx & 127;
                hs4[(size_t)b * (HR / 4) + c] = __ldcg(hsrc + idx);
            }
        }
        __syncthreads();

        float sv[3];
        #pragma unroll 1
        for (int g = 0; g < 8; g++) {       // batch quad {g, g+8, g+16, g+24}
            const ulonglong2* hA = (const ulonglong2*)(hs + (size_t)(g)      * HR);
            const ulonglong2* hC = (const ulonglong2*)(hs + (size_t)(g + 8)  * HR);
            const ulonglong2* hB = (const ulonglong2*)(hs + (size_t)(g + 16) * HR);
            const ulonglong2* hD = (const ulonglong2*)(hs + (size_t)(g + 24) * HR);
            ull aA[3], aB[3], aC[3], aD[3];
            #pragma unroll
            for (int rI = 0; rI < 3; rI++) { aA[rI]=0ull; aB[rI]=0ull; aC[rI]=0ull; aD[rI]=0ull; }
            #pragma unroll
            for (int c = 0; c < 4; c++) {
                ulonglong2 vA = hA[c * 32 + lane];   // float2 in smem IS a packed f32x2
                ulonglong2 vB = hB[c * 32 + lane];
                ulonglong2 vC = hC[c * 32 + lane];
                ulonglong2 vD = hD[c * 32 + lane];
                #pragma unroll
                for (int rI = 0; rI < 3; rI++) {
                    ull w0 = wf2[rI][c * 2], w1 = wf2[rI][c * 2 + 1];
                    aA[rI] = ffma2(w0, vA.x, aA[rI]); aA[rI] = ffma2(w1, vA.y, aA[rI]);
                    aB[rI] = ffma2(w0, vB.x, aB[rI]); aB[rI] = ffma2(w1, vB.y, aB[rI]);
                    aC[rI] = ffma2(w0, vC.x, aC[rI]); aC[rI] = ffma2(w1, vC.y, aC[rI]);
                    aD[rI] = ffma2(w0, vD.x, aD[rI]); aD[rI] = ffma2(w1, vD.y, aD[rI]);
                }
            }
            const bool mine = (lane & 7) == g;
            #pragma unroll
            for (int rI = 0; rI < 3; rI++) {
                float x, y;
                f2unpack(aA[rI], x, y); float vA_ = x + y;
                f2unpack(aB[rI], x, y); float vB_ = x + y;
                f2unpack(aC[rI], x, y); float vC_ = x + y;
                f2unpack(aD[rI], x, y); float vD_ = x + y;
                float fA = vA_ + __shfl_xor_sync(0xffffffffu, vA_, 16);
                float fB = vB_ + __shfl_xor_sync(0xffffffffu, vB_, 16);
                float fC = vC_ + __shfl_xor_sync(0xffffffffu, vC_, 16);
                float fD = vD_ + __shfl_xor_sync(0xffffffffu, vD_, 16);
                float xx = (lane & 16) ? fB : fA;     // quadrant (bit16,bit8): A,B,C,D
                float yy = (lane & 16) ? fD : fC;
                float fx = xx + __shfl_xor_sync(0xffffffffu, xx, 8);
                float fy = yy + __shfl_xor_sync(0xffffffffu, yy, 8);
                float z = (lane & 8) ? fy : fx;
                z += __shfl_xor_sync(0xffffffffu, z, 4);
                z += __shfl_xor_sync(0xffffffffu, z, 2);
                z += __shfl_xor_sync(0xffffffffu, z, 1);
                if (mine) sv[rI] = z;                 // lane g+8m <- its batch's sum
            }
        }

        // gate math (lane == local batch, one unit per thread)
        {
            float* hnb = g_h + ((size_t)(dir * 2 + bufn) * BB + bglob) * HH;
            float hr = sv[0] + bhh[0];
            float hz = sv[1] + bhh[1];
            float hn = sv[2] + bhh[2];
            float rg = 1.f / (1.f + __expf(-(xr + hr)));
            float zg = 1.f / (1.f + __expf(-(xz + hz)));
            float ng = tanhf(xn + rg * hn);
            float hp = hs[(size_t)lane * HR + u];
            float hv = (1.f - zg) * ng + zg * hp;
            hnb[u] = hv;
            if (layer == 0)
                g_out0[((size_t)bglob * TT + t) * (2 * HH) + dir * HH + u] = hv;
        }

        // barrier: publish h_new, prefetch next xg while others arrive, then wait
        unsigned my = grp_arrive(gid);
        if (s + 1 < TT) {
            int tn = dir ? (TT - 2 - s) : (s + 1);
            const float* xgn = g_xg + (((size_t)dir * TT + tn) * BB + bglob) * G3;
            xr = __ldg(xgn + u);
            xz = __ldg(xgn + HH + u);
            xn = __ldg(xgn + 2 * HH + u);
        }
        grp_wait(gid, my);
    }
}

// ---------------- FC head: out[b][c] = cat(hT_f, hT_b) . fc_w[c] + fc_b[c] -----
__global__ void fc_kernel(const float* __restrict__ fc_w, const float* __restrict__ fc_b,
                          float* __restrict__ out) {
    int b = blockIdx.x;
    int c = threadIdx.x >> 5;
    int lane = threadIdx.x & 31;
    // final state lands in buf 0 after 512 steps
    const float* hf = g_h + (size_t)b * HH;                            // dir0 buf0
    const float* hb = g_h + (size_t)2 * BB * HH + (size_t)b * HH;      // dir1 buf0
    const float* w = fc_w + c * (2 * HH);
    float s = 0.f;
    for (int k = lane; k < HH; k += 32) {
        s = fmaf(hf[k], w[k], s);
        s = fmaf(hb[k], w[HH + k], s);
    }
    #pragma unroll
    for (int off = 16; off; off >>= 1) s += __shfl_xor_sync(0xffffffffu, s, off);
    if (lane == 0) out[b * 10 + c] = s + fc_b[c];
}

// ---------------- launch ----------------
extern "C" void kernel_launch(void* const* d_in, const int* in_sizes, int n_in,
                              void* d_out, int out_size) {
    (void)in_sizes; (void)n_in; (void)out_size;
    const int*   sentence = (const int*)  d_in[0];
    const float* emb      = (const float*)d_in[1];
    const float* w_ih_l0  = (const float*)d_in[2];
    const float* w_hh_l0  = (const float*)d_in[3];
    const float* b_ih_l0  = (const float*)d_in[4];
    const float* b_hh_l0  = (const float*)d_in[5];
    const float* w_ih_l1  = (const float*)d_in[6];
    const float* w_hh_l1  = (const float*)d_in[7];
    const float* b_ih_l1  = (const float*)d_in[8];
    const float* b_hh_l1  = (const float*)d_in[9];
    const float* fc_w     = (const float*)d_in[10];
    const float* fc_b     = (const float*)d_in[11];
    float* out = (float*)d_out;

    const int SCAN_SMEM = 32 * HR * 4;   // 66048 bytes (padded rows)
    cudaFuncSetAttribute(scan_kernel, cudaFuncAttributeMaxDynamicSharedMemorySize, SCAN_SMEM);

    embed_kernel<<<BB * TT, 64>>>(sentence, emb);

    // layer 0
    inproj_kernel<<<dim3((BB * TT) / 128, G3 / 128, 2), 256>>>(w_ih_l0, b_ih_l0, EE, 0);
    scan_kernel<<<128, 512, SCAN_SMEM>>>(w_hh_l0, b_hh_l0, 0);

    // layer 1
    inproj_kernel<<<dim3((BB * TT) / 128, G3 / 128, 2), 256>>>(w_ih_l1, b_ih_l1, 2 * HH, 1);
    scan_kernel<<<128, 512, SCAN_SMEM>>>(w_hh_l1, b_hh_l1, 1);

    fc_kernel<<<BB, 320>>>(fc_w, fc_b, out);
}

// round 17
// speedup vs baseline: 1.2212x; 1.2212x over previous
#include <cuda_runtime.h>
#include <cuda_bf16.h>
#include <math.h>
#include <stdint.h>

// Shapes (fixed by the problem)
#define BB 64      // batch
#define TT 512     // seq len
#define EE 256     // embed dim
#define HH 512     // hidden
#define G3 1536    // 3*H
#define HR 516     // padded smem row stride for h (floats)

typedef unsigned long long ull;

// ---------------- scratch (device globals; no allocation allowed) ------------
__device__ __nv_bfloat16 g_ah[(size_t)BB * TT * 1024];   // activations hi (row stride = K)
__device__ __nv_bfloat16 g_al[(size_t)BB * TT * 1024];   // activations lo
__device__ __nv_bfloat16 g_wh[(size_t)2 * G3 * 1024];    // w_ih hi
__device__ __nv_bfloat16 g_wl[(size_t)2 * G3 * 1024];    // w_ih lo
__device__ float g_xg[(size_t)2 * TT * BB * G3];         // [dir][t][b][3H] input-gate proj
__device__ float g_h[(size_t)2 * 2 * BB * HH];           // [dir][buf][b][H] ping-pong state
__device__ unsigned g_cnt[128];                          // per-group barrier counters (sep lines)
__device__ volatile unsigned g_gen[128];

// ---------------- f32x2 packed helpers (scan) ----------------
__device__ __forceinline__ ull f2pack(float x, float y) {
    ull r; asm("mov.b64 %0,{%1,%2};" : "=l"(r) : "f"(x), "f"(y)); return r;
}
__device__ __forceinline__ ull ffma2(ull a, ull b, ull c) {
    ull d; asm("fma.rn.f32x2 %0,%1,%2,%3;" : "=l"(d) : "l"(a), "l"(b), "l"(c)); return d;
}
__device__ __forceinline__ void f2unpack(ull p, float& x, float& y) {
    asm("mov.b64 {%0,%1},%2;" : "=f"(x), "=f"(y) : "l"(p));
}

// ---------------- bf16 split helpers ----------------
__device__ __forceinline__ unsigned pk(__nv_bfloat16 a, __nv_bfloat16 b) {
    unsigned short x = *(unsigned short*)&a, y = *(unsigned short*)&b;
    return (unsigned)x | ((unsigned)y << 16);
}
__device__ __forceinline__ void fsplit(float v, __nv_bfloat16& h, __nv_bfloat16& l) {
    h = __float2bfloat16(v);
    l = __float2bfloat16(v - __bfloat162float(h));
}

// ---------------- split atomic-counter grid barrier (32-CTA groups) ----------
__device__ __forceinline__ unsigned grp_arrive(int gid) {
    __threadfence();
    __syncthreads();
    unsigned my = 0;
    if (threadIdx.x == 0) {
        volatile unsigned* gen = &g_gen[gid * 32];
        my = *gen;
        if (atomicAdd(&g_cnt[gid * 32], 1) == 31) {
            atomicExch(&g_cnt[gid * 32], 0);
            __threadfence();
            *gen = my + 1;
        }
    }
    return my;   // meaningful on thread 0 only
}
__device__ __forceinline__ void grp_wait(int gid, unsigned my) {
    if (threadIdx.x == 0) {
        volatile unsigned* gen = &g_gen[gid * 32];
        while (*gen == my) { }
    }
    __syncthreads();
    __threadfence();
}

// ---------------- mma.sync / ldmatrix / cp.async helpers (sm_80+ features) ---
__device__ __forceinline__ uint32_t smem_u32(const void* p) {
    uint32_t a;
    asm("{ .reg .u64 t; cvta.to.shared.u64 t, %1; cvt.u32.u64 %0, t; }" : "=r"(a) : "l"(p));
    return a;
}
__device__ __forceinline__ void ldsm4(unsigned& r0, unsigned& r1, unsigned& r2, unsigned& r3,
                                      uint32_t addr) {
    asm volatile("ldmatrix.sync.aligned.m8n8.x4.shared.b16 {%0,%1,%2,%3}, [%4];"
                 : "=r"(r0), "=r"(r1), "=r"(r2), "=r"(r3) : "r"(addr));
}
__device__ __forceinline__ void mma16816(float* d, const unsigned* a, unsigned b0, unsigned b1) {
    asm volatile(
        "mma.sync.aligned.m16n8k16.row.col.f32.bf16.bf16.f32 "
        "{%0,%1,%2,%3},{%4,%5,%6,%7},{%8,%9},{%0,%1,%2,%3};"
        : "+f"(d[0]), "+f"(d[1]), "+f"(d[2]), "+f"(d[3])
        : "r"(a[0]), "r"(a[1]), "r"(a[2]), "r"(a[3]), "r"(b0), "r"(b1));
}
__device__ __forceinline__ void cp16(uint32_t dst, const void* src) {
    size_t g = __cvta_generic_to_global(src);
    asm volatile("cp.async.cg.shared.global [%0], [%1], 16;" :: "r"(dst), "l"(g) : "memory");
}

// ---------------- embedding gather -> bf16 hi/lo ----------------
__global__ void embed_kernel(const int* __restrict__ sent, const float* __restrict__ emb) {
    int row = blockIdx.x;                 // row = b*T + t
    int idx = sent[row];
    const float4* src = (const float4*)(emb + (size_t)idx * EE);
    float4 v = src[threadIdx.x];          // 64 threads * 4 floats = 256
    __nv_bfloat16 h0, h1, h2, h3, l0, l1, l2, l3;
    fsplit(v.x, h0, l0); fsplit(v.y, h1, l1); fsplit(v.z, h2, l2); fsplit(v.w, h3, l3);
    unsigned* ah = (unsigned*)(g_ah + (size_t)row * EE);
    unsigned* al = (unsigned*)(g_al + (size_t)row * EE);
    ah[threadIdx.x * 2]     = pk(h0, h1);
    ah[threadIdx.x * 2 + 1] = pk(h2, h3);
    al[threadIdx.x * 2]     = pk(l0, l1);
    al[threadIdx.x * 2 + 1] = pk(l2, l3);
}

// ---------------- w_ih fp32 -> bf16 hi/lo ----------------
__global__ void convw_kernel(const float* __restrict__ src, int n) {
    int i = (blockIdx.x * blockDim.x + threadIdx.x) * 4;
    if (i >= n) return;
    float4 v = *(const float4*)(src + i);
    __nv_bfloat16 h0, h1, h2, h3, l0, l1, l2, l3;
    fsplit(v.x, h0, l0); fsplit(v.y, h1, l1); fsplit(v.z, h2, l2); fsplit(v.w, h3, l3);
    unsigned* wh = (unsigned*)(g_wh + i);
    unsigned* wl = (unsigned*)(g_wl + i);
    wh[0] = pk(h0, h1); wh[1] = pk(h2, h3);
    wl[0] = pk(l0, l1); wl[1] = pk(l2, l3);
}

// ---------------- tensor-core input projection (mma.sync bf16 split) ---------
// xg[dir][t][b][n] = sum_k A[m][k]*W[dir][n][k] + b_ih[n], 3 passes:
//   D += Ah*Bh ; D += Ah*Bl ; D += Al*Bh   (fp32 accum; lo*lo ~2^-18, dropped)
// Tile 128x128, BK=64 bf16 (128B rows, SW128 xor swizzle), 8 warps a 64x32,
// m16n8k16 mma + ldmatrix.x4, cp.async double-buffered. NC = 3*K/64 chunks.
#define TCPART 16384                    // one operand tile: 128 rows x 128B
#define TCBUF  (2 * TCPART)             // A|B
#define TCS    (2 * TCBUF)              // double buffer = 65536 B

__global__ __launch_bounds__(256, 1) void tcgemm_kernel(const float* __restrict__ bias,
                                                        int K, int NC) {
    extern __shared__ __align__(16) char smem[];
    uint32_t sb = smem_u32(smem);
    const int tid = threadIdx.x, wid = tid >> 5, lane = tid & 31;
    const int m0 = blockIdx.x * 128, n0 = blockIdx.y * 128, dir = blockIdx.z;
    const int warpM = (wid >> 2) * 64, warpN = (wid & 3) * 32;
    const int KC = NC / 3;

    float acc[4][4][4];
    #pragma unroll
    for (int mi = 0; mi < 4; mi++)
        #pragma unroll
        for (int nj = 0; nj < 4; nj++)
            #pragma unroll
            for (int e = 0; e < 4; e++) acc[mi][nj][e] = 0.f;

    // prefetch chunk c into buffer c&1 (A rows then B rows, SW128 swizzled)
    auto do_prefetch = [&](int c) {
        int pass = c / KC, kc = c - pass * KC;
        const __nv_bfloat16* As = (pass == 2) ? g_al : g_ah;
        const __nv_bfloat16* Bs = (pass == 1) ? g_wl : g_wh;
        uint32_t base = sb + (uint32_t)(c & 1) * TCBUF;
        #pragma unroll
        for (int i = 0; i < 4; i++) {
            int task = tid + i * 256;          // 1024 16B chunks per operand
            int row = task >> 3, ck = task & 7;
            uint32_t soff = (uint32_t)(row * 128 + ((ck ^ (row & 7)) << 4));
            cp16(base + soff,
                 (const char*)As + ((size_t)(m0 + row) * K + kc * 64 + ck * 8) * 2);
            cp16(base + TCPART + soff,
                 (const char*)Bs + ((size_t)(dir * G3 + n0 + row) * K + kc * 64 + ck * 8) * 2);
        }
        asm volatile("cp.async.commit_group;" ::: "memory");
    };

    do_prefetch(0);

    for (int c = 0; c < NC; c++) {
        if (c + 1 < NC) {
            do_prefetch(c + 1);
            asm volatile("cp.async.wait_group 1;" ::: "memory");
        } else {
            asm volatile("cp.async.wait_group 0;" ::: "memory");
        }
        __syncthreads();
        uint32_t Ab = sb + (uint32_t)(c & 1) * TCBUF;
        uint32_t Bb = Ab + TCPART;
        #pragma unroll
        for (int kh = 0; kh < 4; kh++) {       // 4 x k16 within BK=64
            unsigned af[4][4];
            #pragma unroll
            for (int mi = 0; mi < 4; mi++) {
                int row = warpM + mi * 16 + (lane & 15);
                int ck = 2 * kh + (lane >> 4);
                uint32_t a = Ab + row * 128 + ((ck ^ (row & 7)) << 4);
                ldsm4(af[mi][0], af[mi][1], af[mi][2], af[mi][3], a);
            }
            unsigned bf[2][4];
            #pragma unroll
            for (int nj2 = 0; nj2 < 2; nj2++) {
                int row = warpN + nj2 * 16 + (lane & 15);
                int ck = 2 * kh + (lane >> 4);
                uint32_t a = Bb + row * 128 + ((ck ^ (row & 7)) << 4);
                ldsm4(bf[nj2][0], bf[nj2][1], bf[nj2][2], bf[nj2][3], a);
            }
            #pragma unroll
            for (int mi = 0; mi < 4; mi++)
                #pragma unroll
                for (int nj = 0; nj < 4; nj++) {
                    unsigned b0 = bf[nj >> 1][nj & 1];        // (n rows, k0-7)
                    unsigned b1 = bf[nj >> 1][2 + (nj & 1)];  // (n rows, k8-15)
                    mma16816(acc[mi][nj], af[mi], b0, b1);
                }
        }
        __syncthreads();
    }

    // epilogue: +bias, scatter D(128x128) to g_xg[dir][t][b][3H]
    const float* bp = bias + dir * G3 + n0 + warpN;
    #pragma unroll
    for (int mi = 0; mi < 4; mi++)
        #pragma unroll
        for (int rh = 0; rh < 2; rh++) {
            int mm = m0 + warpM + mi * 16 + (lane >> 2) + rh * 8;
            int b_ = mm >> 9, t_ = mm & 511;       // m = b*512 + t
            float* dst = g_xg + (((size_t)dir * TT + t_) * BB + b_) * G3 + n0 + warpN;
            #pragma unroll
            for (int nj = 0; nj < 4; nj++) {
                int col = nj * 8 + (lane & 3) * 2;
                float2 o;
                o.x = acc[mi][nj][rh * 2 + 0] + bp[col];
                o.y = acc[mi][nj][rh * 2 + 1] + bp[col + 1];
                *(float2*)(dst + col) = o;
            }
        }
}

// ---------------- persistent GRU scan (R11 config; layer0 emits bf16 hi/lo) --
// grid = 128 CTAs x 256 threads: dir(2) x bhalf(2: 32 batches) x ublk(32: 16 units).
__global__ __launch_bounds__(256, 1) void scan_kernel(const float* __restrict__ w_hh,
                                                      const float* __restrict__ b_hh,
                                                      int layer) {
    extern __shared__ float hs[];  // [32][HR] staged h_old (this CTA's 32 batches)
    const int bid = blockIdx.x;
    const int dir = bid >> 6;
    const int rr = bid & 63;
    const int bhalf = rr >> 5;
    const int ublk = rr & 31;
    const int gid = dir * 2 + bhalf;       // barrier group (32 CTAs)
    const int tid = threadIdx.x;
    const int wid = tid >> 5, lane = tid & 31;
    const int u_base = ublk * 16 + wid * 2;

    ull wf2[6][8];
    float bhh[6];
    #pragma unroll
    for (int ul = 0; ul < 2; ul++)
        #pragma unroll
        for (int g = 0; g < 3; g++) {
            int row = g * HH + u_base + ul;
            const float4* wr = (const float4*)(w_hh + ((size_t)dir * G3 + row) * HH);
            #pragma unroll
            for (int c = 0; c < 4; c++) {
                float4 wv = __ldg(wr + c * 32 + lane);
                wf2[ul * 3 + g][c * 2 + 0] = f2pack(wv.x, wv.y);
                wf2[ul * 3 + g][c * 2 + 1] = f2pack(wv.z, wv.w);
            }
            bhh[ul * 3 + g] = __ldg(b_hh + dir * G3 + row);
        }

    {
        float* z = g_h + (size_t)(dir * 2 + 0) * BB * HH;
        for (int i = tid; i < 32 * 16; i += 256) {
            int bl = i >> 4, uu = i & 15;
            z[(size_t)(bhalf * 32 + bl) * HH + ublk * 16 + uu] = 0.f;
        }
    }
    {
        unsigned my = grp_arrive(gid);
        grp_wait(gid, my);
    }

    const int bglob = bhalf * 32 + lane;

    int t0 = dir ? (TT - 1) : 0;
    const float* xgb0 = g_xg + (((size_t)dir * TT + t0) * BB + bglob) * G3;
    float2 xr = __ldg((const float2*)(xgb0 + u_base));
    float2 xz = __ldg((const float2*)(xgb0 + HH + u_base));
    float2 xn = __ldg((const float2*)(xgb0 + 2 * HH + u_base));

    for (int s = 0; s < TT; s++) {
        const int t = dir ? (TT - 1 - s) : s;
        const int bufo = s & 1;
        const int bufn = bufo ^ 1;

        {
            const float4* hsrc = (const float4*)(g_h + ((size_t)(dir * 2 + bufo) * BB + bhalf * 32) * HH);
            float4* hs4 = (float4*)hs;
            #pragma unroll
            for (int p = 0; p < 16; p++) {
                int idx = tid + p * 256;
                int b = idx >> 7, c = idx & 127;
                hs4[(size_t)b * (HR / 4) + c] = __ldcg(hsrc + idx);
            }
        }
        __syncthreads();

        float sv[6];
        #pragma unroll 1
        for (int g = 0; g < 8; g++) {       // batch quad {g, g+8, g+16, g+24}
            const ulonglong2* hA = (const ulonglong2*)(hs + (size_t)(g)      * HR);
            const ulonglong2* hC = (const ulonglong2*)(hs + (size_t)(g + 8)  * HR);
            const ulonglong2* hB = (const ulonglong2*)(hs + (size_t)(g + 16) * HR);
            const ulonglong2* hD = (const ulonglong2*)(hs + (size_t)(g + 24) * HR);
            ull aA[6], aB[6], aC[6], aD[6];
            #pragma unroll
            for (int rI = 0; rI < 6; rI++) { aA[rI]=0ull; aB[rI]=0ull; aC[rI]=0ull; aD[rI]=0ull; }
            #pragma unroll
            for (int c = 0; c < 4; c++) {
                ulonglong2 vA = hA[c * 32 + lane];
                ulonglong2 vB = hB[c * 32 + lane];
                ulonglong2 vC = hC[c * 32 + lane];
                ulonglong2 vD = hD[c * 32 + lane];
                #pragma unroll
                for (int rI = 0; rI < 6; rI++) {
                    ull w0 = wf2[rI][c * 2], w1 = wf2[rI][c * 2 + 1];
                    aA[rI] = ffma2(w0, vA.x, aA[rI]); aA[rI] = ffma2(w1, vA.y, aA[rI]);
                    aB[rI] = ffma2(w0, vB.x, aB[rI]); aB[rI] = ffma2(w1, vB.y, aB[rI]);
                    aC[rI] = ffma2(w0, vC.x, aC[rI]); aC[rI] = ffma2(w1, vC.y, aC[rI]);
                    aD[rI] = ffma2(w0, vD.x, aD[rI]); aD[rI] = ffma2(w1, vD.y, aD[rI]);
                }
            }
            const bool mine = (lane & 7) == g;
            #pragma unroll
            for (int rI = 0; rI < 6; rI++) {
                float x, y;
                f2unpack(aA[rI], x, y); float vA_ = x + y;
                f2unpack(aB[rI], x, y); float vB_ = x + y;
                f2unpack(aC[rI], x, y); float vC_ = x + y;
                f2unpack(aD[rI], x, y); float vD_ = x + y;
                float fA = vA_ + __shfl_xor_sync(0xffffffffu, vA_, 16);
                float fB = vB_ + __shfl_xor_sync(0xffffffffu, vB_, 16);
                float fC = vC_ + __shfl_xor_sync(0xffffffffu, vC_, 16);
                float fD = vD_ + __shfl_xor_sync(0xffffffffu, vD_, 16);
                float xx = (lane & 16) ? fB : fA;
                float yy = (lane & 16) ? fD : fC;
                float fx = xx + __shfl_xor_sync(0xffffffffu, xx, 8);
                float fy = yy + __shfl_xor_sync(0xffffffffu, yy, 8);
                float z = (lane & 8) ? fy : fx;
                z += __shfl_xor_sync(0xffffffffu, z, 4);
                z += __shfl_xor_sync(0xffffffffu, z, 2);
                z += __shfl_xor_sync(0xffffffffu, z, 1);
                if (mine) sv[rI] = z;
            }
        }

        // gate math (lane == local batch)
        {
            float* hnb = g_h + ((size_t)(dir * 2 + bufn) * BB + bglob) * HH;
            float xrv[2] = {xr.x, xr.y}, xzv[2] = {xz.x, xz.y}, xnv[2] = {xn.x, xn.y};
            float hvv[2];
            #pragma unroll
            for (int ul = 0; ul < 2; ul++) {
                int u = u_base + ul;
                float hr = sv[ul * 3 + 0] + bhh[ul * 3 + 0];
                float hz = sv[ul * 3 + 1] + bhh[ul * 3 + 1];
                float hn = sv[ul * 3 + 2] + bhh[ul * 3 + 2];
                float rg = 1.f / (1.f + __expf(-(xrv[ul] + hr)));
                float zg = 1.f / (1.f + __expf(-(xzv[ul] + hz)));
                float ng = tanhf(xnv[ul] + rg * hn);
                float hp = hs[(size_t)lane * HR + u];
                float hv = (1.f - zg) * ng + zg * hp;
                hnb[u] = hv;
                hvv[ul] = hv;
            }
            if (layer == 0) {
                // layer-1 GEMM A operand: bf16 hi/lo, layout [b*T+t][2H], K=1024
                size_t off = ((size_t)bglob * TT + t) * (size_t)(2 * HH) + dir * HH + u_base;
                __nv_bfloat16 h0, l0, h1, l1;
                fsplit(hvv[0], h0, l0);
                fsplit(hvv[1], h1, l1);
                *(unsigned*)(g_ah + off) = pk(h0, h1);
                *(unsigned*)(g_al + off) = pk(l0, l1);
            }
        }

        unsigned my = grp_arrive(gid);
        if (s + 1 < TT) {
            int tn = dir ? (TT - 2 - s) : (s + 1);
            const float* xgn = g_xg + (((size_t)dir * TT + tn) * BB + bglob) * G3;
            xr = __ldg((const float2*)(xgn + u_base));
            xz = __ldg((const float2*)(xgn + HH + u_base));
            xn = __ldg((const float2*)(xgn + 2 * HH + u_base));
        }
        grp_wait(gid, my);
    }
}

// ---------------- FC head: out[b][c] = cat(hT_f, hT_b) . fc_w[c] + fc_b[c] -----
__global__ void fc_kernel(const float* __restrict__ fc_w, const float* __restrict__ fc_b,
                          float* __restrict__ out) {
    int b = blockIdx.x;
    int c = threadIdx.x >> 5;
    int lane = threadIdx.x & 31;
    const float* hf = g_h + (size_t)b * HH;                            // dir0 buf0
    const float* hb = g_h + (size_t)2 * BB * HH + (size_t)b * HH;      // dir1 buf0
    const float* w = fc_w + c * (2 * HH);
    float s = 0.f;
    for (int k = lane; k < HH; k += 32) {
        s = fmaf(hf[k], w[k], s);
        s = fmaf(hb[k], w[HH + k], s);
    }
    #pragma unroll
    for (int off = 16; off; off >>= 1) s += __shfl_xor_sync(0xffffffffu, s, off);
    if (lane == 0) out[b * 10 + c] = s + fc_b[c];
}

// ---------------- launch ----------------
extern "C" void kernel_launch(void* const* d_in, const int* in_sizes, int n_in,
                              void* d_out, int out_size) {
    (void)in_sizes; (void)n_in; (void)out_size;
    const int*   sentence = (const int*)  d_in[0];
    const float* emb      = (const float*)d_in[1];
    const float* w_ih_l0  = (const float*)d_in[2];
    const float* w_hh_l0  = (const float*)d_in[3];
    const float* b_ih_l0  = (const float*)d_in[4];
    const float* b_hh_l0  = (const float*)d_in[5];
    const float* w_ih_l1  = (const float*)d_in[6];
    const float* w_hh_l1  = (const float*)d_in[7];
    const float* b_ih_l1  = (const float*)d_in[8];
    const float* b_hh_l1  = (const float*)d_in[9];
    const float* fc_w     = (const float*)d_in[10];
    const float* fc_b     = (const float*)d_in[11];
    float* out = (float*)d_out;

    const int SCAN_SMEM = 32 * HR * 4;   // 66048 bytes (padded rows)
    cudaFuncSetAttribute(scan_kernel, cudaFuncAttributeMaxDynamicSharedMemorySize, SCAN_SMEM);
    cudaFuncSetAttribute(tcgemm_kernel, cudaFuncAttributeMaxDynamicSharedMemorySize, TCS);

    embed_kernel<<<BB * TT, 64>>>(sentence, emb);                 // -> g_ah/g_al (K=256)

    // layer 0
    convw_kernel<<<(2 * G3 * EE) / 1024, 256>>>(w_ih_l0, 2 * G3 * EE);
    tcgemm_kernel<<<dim3((BB * TT) / 128, G3 / 128, 2), 256, TCS>>>(b_ih_l0, EE, 3 * EE / 64);
    scan_kernel<<<128, 256, SCAN_SMEM>>>(w_hh_l0, b_hh_l0, 0);    // -> g_ah/g_al (K=1024)

    // layer 1
    convw_kernel<<<(2 * G3 * 1024) / 1024, 256>>>(w_ih_l1, 2 * G3 * 1024);
    tcgemm_kernel<<<dim3((BB * TT) / 128, G3 / 128, 2), 256, TCS>>>(b_ih_l1, 2 * HH, 3 * 1024 / 64);
    scan_kernel<<<128, 256, SCAN_SMEM>>>(w_hh_l1, b_hh_l1, 1);

    fc_kernel<<<BB, 320>>>(fc_w, fc_b, out);
}